// round 12
// baseline (speedup 1.0000x reference)
#include <cuda_runtime.h>
#include <cuda_bf16.h>
#include <math.h>

// BERTEmbedding: out[row, 0:256]   = x[row,0:10] @ W[256,10]^T + b
//                out[row, 256:512] = sinusoidal PE at pos = doy[row]
// rows = B*S = 131072; output 268 MB fp32 -> HBM-write-bound target.
//
// R12: fully decoupled warps -- no smem staging, no __syncthreads (R11's
// barrier parked the cheap PE warps behind the obs warps each tile; alu 26%
// was staging/addressing overhead). Warps 0-3: obs, x read as 5 uniform
// float2 LDGs per row (1 L1 wavefront each, cheaper than 10 LDS broadcasts),
// 2 cols/thread, STG.64. Warps 4-7: PE, uniform doy LDG + MUFU sincos,
// unrolled x4, free-running store stream. Pointer-increment addressing.

#define TPB   256
#define NBLK  888   // 148 SMs * 6 resident blocks; grid-stride over rows

__global__ void __launch_bounds__(TPB, 6) bert_embed_kernel(
    const float* __restrict__ x,      // [rows, 10]
    const int*   __restrict__ doy,    // [rows]
    const float* __restrict__ W,      // [256, 10] row-major
    const float* __restrict__ bias,   // [256]
    float*       __restrict__ out,    // [rows, 512]
    int nrows)
{
    const int t = threadIdx.x;
    const int w = t >> 5;
    const int l = t & 31;

    const int    rstride = gridDim.x;                 // rows advance per iter
    const size_t pstep   = (size_t)rstride * 256;     // float2s per iter

    float2* o2 = reinterpret_cast<float2*>(out);      // [rows][256]

    if (w < 4) {
        // ---------------- obs warps ----------------
        const int c0 = (w * 32 + l) * 2;              // first of 2 output cols
        float2 wv[10];
        #pragma unroll
        for (int f = 0; f < 10; ++f)
            wv[f] = make_float2(W[c0 * 10 + f], W[(c0 + 1) * 10 + f]);
        const float2 bv = make_float2(bias[c0], bias[c0 + 1]);

        int row = blockIdx.x;
        float2*       op = o2 + (size_t)row * 256 + (c0 >> 1);
        const float2* xp = reinterpret_cast<const float2*>(x) + (size_t)row * 5;
        const size_t  xstep = (size_t)rstride * 5;

        for (; row < nrows; row += rstride, op += pstep, xp += xstep) {
            // 10 x values as 5 uniform float2 loads (warp-broadcast)
            float xv[10];
            #pragma unroll
            for (int k2 = 0; k2 < 5; ++k2) {
                const float2 p = __ldg(xp + k2);
                xv[2 * k2]     = p.x;
                xv[2 * k2 + 1] = p.y;
            }
            float2 acc = bv;
            #pragma unroll
            for (int f = 0; f < 10; ++f) {
                acc.x = fmaf(xv[f], wv[f].x, acc.x);
                acc.y = fmaf(xv[f], wv[f].y, acc.y);
            }
            *op = acc;
        }
    } else {
        // ---------------- PE warps ----------------
        const int   i   = (w - 4) * 32 + l;            // 0..127
        const float kk  = -9.210340371976184f / 256.0f; // -ln(10000)/D
        const float div = expf(kk * (float)(2 * i));

        int row = blockIdx.x;
        float2* op = o2 + (size_t)row * 256 + 128 + i;

        // unrolled x4 over the grid-stride (tail handled by inner guard)
        for (; row < nrows; row += 4 * rstride, op += 4 * pstep) {
            #pragma unroll
            for (int u = 0; u < 4; ++u) {
                const int r = row + u * rstride;
                if (r < nrows) {
                    const float pos = (float)__ldg(doy + r);
                    float2 v;
                    __sincosf(pos * div, &v.x, &v.y);  // RRO + MUFU pair
                    op[u * pstep] = v;
                }
            }
        }
    }
}

extern "C" void kernel_launch(void* const* d_in, const int* in_sizes, int n_in,
                              void* d_out, int out_size) {
    const float* x    = (const float*)d_in[0];   // input_sequence [B,S,10]
    const int*   doy  = (const int*)  d_in[1];   // doy_sequence   [B,S]
    const float* W    = (const float*)d_in[2];   // W [256,10]
    const float* bias = (const float*)d_in[3];   // b [256]
    float*       out  = (float*)d_out;           // [B,S,512]

    const int nrows = in_sizes[1];               // B*S

    bert_embed_kernel<<<NBLK, TPB>>>(x, doy, W, bias, out, nrows);
}

// round 14
// speedup vs baseline: 1.5347x; 1.5347x over previous
#include <cuda_runtime.h>
#include <cuda_bf16.h>
#include <math.h>

// BERTEmbedding: out[row, 0:256]   = x[row,0:10] @ W[256,10]^T + b
//                out[row, 256:512] = sinusoidal PE at pos = doy[row]
// rows = B*S = 131072; output 268 MB fp32 -> HBM-write-bound target.
//
// R13 = R11 obs pipeline + decoupled PE warps.
//  - Obs warps 0-3: double-buffered smem x staging (tile R=8), synced by a
//    NAMED barrier (bar.sync 1, 128) scoped to the obs half only; x read from
//    smem as float2 (5 LDS.64/row, was 10 LDS.32).
//  - PE warps 4-7: free-running (no smem/barriers): uniform doy LDG + MUFU
//    sincos + STG.64 per row; sprint ahead, then exit and donate issue slots.
// (R12 post-mortem: removing the staging made obs warps MLP~1 latency-bound,
// 88.5us. The pipeline is load-bearing; only the PE coupling was waste.)

#define TPB   256
#define R     8
#define NBLK  888   // 148 SMs * 6 resident blocks

__global__ void __launch_bounds__(TPB, 6) bert_embed_kernel(
    const float* __restrict__ x,      // [rows, 10]
    const int*   __restrict__ doy,    // [rows]
    const float* __restrict__ W,      // [256, 10] row-major
    const float* __restrict__ bias,   // [256]
    float*       __restrict__ out,    // [rows, 512]
    int nrows)
{
    __shared__ float s_x[2][R * 10];      // staged x tile (80 floats/buf)

    const int t = threadIdx.x;
    float2* o2 = reinterpret_cast<float2*>(out);      // [rows][256]
    const int ntiles = (nrows + R - 1) / R;

    if (t < 128) {
        // ---------------- obs half: pipelined via smem ----------------
        const int c0 = t * 2;                         // output cols 2t, 2t+1
        float2 wv[10];
        #pragma unroll
        for (int f = 0; f < 10; ++f)
            wv[f] = make_float2(W[c0 * 10 + f], W[(c0 + 1) * 10 + f]);
        const float2 bv = make_float2(bias[c0], bias[c0 + 1]);

        // stage first tile (threads 0..79)
        int tile = blockIdx.x;
        if (t < R * 10) {
            const int gi = tile * R * 10 + t;
            s_x[0][t] = (gi < nrows * 10) ? x[gi] : 0.f;
        }
        asm volatile("bar.sync 1, 128;" ::: "memory");

        int buf = 0;
        for (; tile < ntiles; tile += gridDim.x, buf ^= 1) {
            // prefetch next tile into the other buffer
            const int ntile = tile + gridDim.x;
            if (ntile < ntiles && t < R * 10) {
                const int gi = ntile * R * 10 + t;
                s_x[buf ^ 1][t] = (gi < nrows * 10) ? x[gi] : 0.f;
            }

            const int rowbase = tile * R;
            const float2* sx2 = reinterpret_cast<const float2*>(s_x[buf]);
            #pragma unroll
            for (int r = 0; r < R; ++r) {
                const int row = rowbase + r;
                if (row >= nrows) break;
                float2 acc = bv;
                #pragma unroll
                for (int k2 = 0; k2 < 5; ++k2) {
                    const float2 p = sx2[r * 5 + k2];   // LDS.64 broadcast
                    acc.x = fmaf(p.x, wv[2 * k2].x, acc.x);
                    acc.y = fmaf(p.x, wv[2 * k2].y, acc.y);
                    acc.x = fmaf(p.y, wv[2 * k2 + 1].x, acc.x);
                    acc.y = fmaf(p.y, wv[2 * k2 + 1].y, acc.y);
                }
                o2[(size_t)row * 256 + t] = acc;        // cols 2t, 2t+1
            }
            asm volatile("bar.sync 1, 128;" ::: "memory");
        }
    } else {
        // ---------------- PE half: free-running ----------------
        const int   i   = t - 128;                     // 0..127
        const float kk  = -9.210340371976184f / 256.0f; // -ln(10000)/D
        const float div = expf(kk * (float)(2 * i));

        const size_t pstep = (size_t)gridDim.x * R * 256;  // float2s per tile hop
        int tile = blockIdx.x;
        float2* op = o2 + (size_t)tile * R * 256 + 128 + i;

        for (; tile < ntiles; tile += gridDim.x, op += pstep) {
            const int rowbase = tile * R;
            #pragma unroll
            for (int r = 0; r < R; ++r) {
                const int row = rowbase + r;
                if (row < nrows) {
                    const float pos = (float)__ldg(doy + row);
                    float2 v;
                    __sincosf(pos * div, &v.x, &v.y);  // RRO + MUFU pair
                    op[(size_t)r * 256] = v;
                }
            }
        }
    }
}

extern "C" void kernel_launch(void* const* d_in, const int* in_sizes, int n_in,
                              void* d_out, int out_size) {
    const float* x    = (const float*)d_in[0];   // input_sequence [B,S,10]
    const int*   doy  = (const int*)  d_in[1];   // doy_sequence   [B,S]
    const float* W    = (const float*)d_in[2];   // W [256,10]
    const float* bias = (const float*)d_in[3];   // b [256]
    float*       out  = (float*)d_out;           // [B,S,512]

    const int nrows = in_sizes[1];               // B*S

    bert_embed_kernel<<<NBLK, TPB>>>(x, doy, W, bias, out, nrows);
}

// round 15
// speedup vs baseline: 1.7272x; 1.1255x over previous
#include <cuda_runtime.h>
#include <cuda_bf16.h>
#include <math.h>

// BERTEmbedding: out[row, 0:256]   = x[row,0:10] @ W[256,10]^T + b
//                out[row, 256:512] = sinusoidal PE at pos = doy[row]
// rows = B*S = 131072; output 268 MB fp32 -> HBM-write-bound target.
//
// R15 = R11 skeleton (coupled tile pipeline -- best measured: 44.9us main) with
// issue-slot cuts. R12/R13 post-mortems: decoupling the PE warps breaks the
// phase-locked store wavefront (all 48 warps storing the same rows in the same
// tile window) and regresses; the full-block barrier stays. Changes:
//  1. per-tile base pointer + unrolled imm-offset stores (kills per-row IMAD.WIDE)
//  2. obs x reads as float2 LDS (5/row, was 10 LDS.32)
//  3. x staged with float2 LDGs (threads 0..39)

#define TPB   256
#define R     8
#define NBLK  888   // 148 SMs * 6 resident blocks; grid-stride over tiles

__global__ void __launch_bounds__(TPB, 6) bert_embed_kernel(
    const float* __restrict__ x,      // [rows, 10]
    const int*   __restrict__ doy,    // [rows]
    const float* __restrict__ W,      // [256, 10] row-major
    const float* __restrict__ bias,   // [256]
    float*       __restrict__ out,    // [rows, 512]
    int nrows)
{
    __shared__ float2 s_x2[2][R * 5];     // staged x tile, float2 view
    __shared__ int    s_doy[2][R];

    const int  t      = threadIdx.x;
    const bool is_obs = (t < 128);

    // ---- loop-invariant per-thread constants ----
    float2 wv[10];
    float2 bv  = make_float2(0.f, 0.f);
    float  div = 0.f;
    if (is_obs) {
        const int c0 = t * 2;                          // output cols 2t, 2t+1
        #pragma unroll
        for (int f = 0; f < 10; ++f)
            wv[f] = make_float2(W[c0 * 10 + f], W[(c0 + 1) * 10 + f]);
        bv = make_float2(bias[c0], bias[c0 + 1]);
    } else {
        const int   i = t - 128;
        const float k = -9.210340371976184f / 256.0f;  // -ln(10000)/D
        div = expf(k * (float)(2 * i));
    }

    float2* o2 = reinterpret_cast<float2*>(out);       // [rows][256]
    const float2* x2 = reinterpret_cast<const float2*>(x);  // [rows*5]

    const int ntiles  = (nrows + R - 1) / R;
    const int nx2     = nrows * 5;                     // total float2s in x

    // stage first tile: threads 0..39 -> x (40 float2), 96..103 -> doy
    int tile = blockIdx.x;
    {
        const int base = tile * R;
        if (t < R * 5) {
            const int gi = base * 5 + t;
            s_x2[0][t] = (gi < nx2) ? __ldg(x2 + gi) : make_float2(0.f, 0.f);
        } else if (t >= 96 && t < 96 + R) {
            const int r = t - 96;
            s_doy[0][r] = (base + r < nrows) ? doy[base + r] : 0;
        }
    }
    __syncthreads();

    // per-tile output base pointer: row offsets are unrolled immediates
    float2*      op    = o2 + (size_t)tile * R * 256 + (is_obs ? t : t);  // col slot = t for obs (cols 2t), 128+(t-128)=t for PE
    const size_t tstep = (size_t)gridDim.x * R * 256;

    int buf = 0;
    for (; tile < ntiles; tile += gridDim.x, buf ^= 1, op += tstep) {
        // prefetch next tile into the other buffer
        const int ntile = tile + gridDim.x;
        if (ntile < ntiles) {
            const int nb = ntile * R;
            if (t < R * 5) {
                const int gi = nb * 5 + t;
                s_x2[buf ^ 1][t] = (gi < nx2) ? __ldg(x2 + gi)
                                              : make_float2(0.f, 0.f);
            } else if (t >= 96 && t < 96 + R) {
                const int r = t - 96;
                s_doy[buf ^ 1][r] = (nb + r < nrows) ? doy[nb + r] : 0;
            }
        }

        const int rowbase = tile * R;
        if (is_obs) {
            #pragma unroll
            for (int r = 0; r < R; ++r) {
                if (rowbase + r >= nrows) break;
                float2 acc = bv;
                #pragma unroll
                for (int k2 = 0; k2 < 5; ++k2) {
                    const float2 p = s_x2[buf][r * 5 + k2];   // LDS.64 bcast
                    acc.x = fmaf(p.x, wv[2 * k2].x, acc.x);
                    acc.y = fmaf(p.x, wv[2 * k2].y, acc.y);
                    acc.x = fmaf(p.y, wv[2 * k2 + 1].x, acc.x);
                    acc.y = fmaf(p.y, wv[2 * k2 + 1].y, acc.y);
                }
                op[r * 256] = acc;                     // imm offset (r*2KB)
            }
        } else {
            #pragma unroll
            for (int r = 0; r < R; ++r) {
                if (rowbase + r >= nrows) break;
                const float pos = (float)s_doy[buf][r];
                float2 v;
                __sincosf(pos * div, &v.x, &v.y);      // RRO + MUFU pair
                op[r * 256] = v;                       // imm offset
            }
        }
        __syncthreads();
    }
}

extern "C" void kernel_launch(void* const* d_in, const int* in_sizes, int n_in,
                              void* d_out, int out_size) {
    const float* x    = (const float*)d_in[0];   // input_sequence [B,S,10]
    const int*   doy  = (const int*)  d_in[1];   // doy_sequence   [B,S]
    const float* W    = (const float*)d_in[2];   // W [256,10]
    const float* bias = (const float*)d_in[3];   // b [256]
    float*       out  = (float*)d_out;           // [B,S,512]

    const int nrows = in_sizes[1];               // B*S

    bert_embed_kernel<<<NBLK, TPB>>>(x, doy, W, bias, out, nrows);
}